// round 14
// baseline (speedup 1.0000x reference)
#include <cuda_runtime.h>
#include <cuda_fp16.h>
#include <math.h>
#include <stdint.h>

// ---------------- problem dims ----------------
#define B_    512
#define T_    128
#define IDIM  512
#define N0    538
#define N1    358
#define N2    128
#define OUT_  128
#define UNITS 1024

// padded fp16 layouts (all K segments multiples of 64)
#define NP0   2176      // 4*538=2152 -> 17*128
#define KP0   1088      // [x 512 | h0 538->576]
#define NP1   1536      // 4*358=1432 -> 12*128
#define KP1   960       // [h0 576 | h1 358->384]
#define NP2   512       // 4*128
#define KP2   512       // [h1 384 | h2 128]
#define LH0   576
#define LH1   384
#define LH2   128

#define NCTA  148       // 85 L0-group + 53 L1-group + 10 L2-group

// tile: CTA 128x128, BK=64 per main-loop step
#define ROWB     144                 // stage row stride in bytes (128 data + 16 pad)
#define STAGEB   (128*ROWB)          // 18432 B per matrix per stage
#define LDC      132                 // C staging row stride (floats)
#define SMEM_DYN (4*STAGEB + 128)    // 73856 B; Cs (128*132*4 = 67584 B) aliases

// ---------------- device globals ----------------
__device__ __align__(16) __half g_x16[(size_t)B_ * T_ * IDIM];   // transposed: (T, B, IDIM)
__device__ __align__(16) __half g_w0[(size_t)NP0 * KP0];
__device__ __align__(16) __half g_w1[(size_t)NP1 * KP1];
__device__ __align__(16) __half g_w2[(size_t)NP2 * KP2];
__device__ __align__(16) float  g_bc0[NP0];
__device__ __align__(16) float  g_bc1[NP1];
__device__ __align__(16) float  g_bc2[NP2];
__device__ __align__(16) __half g_h16_0[2][B_ * LH0];
__device__ __align__(16) __half g_h16_1[2][B_ * LH1];
__device__ __align__(16) __half g_h16_2[2][B_ * LH2];
__device__ __align__(16) float  g_h32_0[B_ * N0];
__device__ __align__(16) float  g_h32_1[B_ * N1];
__device__ __align__(16) float  g_h32_2[B_ * N2];
__device__ __align__(16) float  g_motor[(size_t)B_ * T_ * OUT_];
__device__ unsigned g_cnt[3][4][T_];     // completion counters per (layer, mrow, t)

// ---------------- PTX helpers ----------------
__device__ __forceinline__ uint32_t s2u(const void* p) {
    return (uint32_t)__cvta_generic_to_shared(p);
}
__device__ __forceinline__ void cpa16(uint32_t dst, const void* src) {
    asm volatile("cp.async.cg.shared.global [%0], [%1], 16;"
                 :: "r"(dst), "l"(src) : "memory");
}
#define CP_COMMIT() asm volatile("cp.async.commit_group;" ::: "memory")
#define CP_WAIT0()  asm volatile("cp.async.wait_group 0;" ::: "memory")

__device__ __forceinline__ void ldsm_x4(uint32_t& r0, uint32_t& r1, uint32_t& r2, uint32_t& r3,
                                        uint32_t addr)
{
    asm volatile("ldmatrix.sync.aligned.m8n8.x4.shared.b16 {%0,%1,%2,%3}, [%4];"
                 : "=r"(r0), "=r"(r1), "=r"(r2), "=r"(r3) : "r"(addr));
}
__device__ __forceinline__ void mma_f16(float& c0, float& c1, float& c2, float& c3,
                                        uint32_t a0, uint32_t a1, uint32_t a2, uint32_t a3,
                                        uint32_t b0, uint32_t b1)
{
    asm volatile("mma.sync.aligned.m16n8k16.row.col.f32.f16.f16.f32 "
                 "{%0,%1,%2,%3}, {%4,%5,%6,%7}, {%8,%9}, {%0,%1,%2,%3};"
                 : "+f"(c0), "+f"(c1), "+f"(c2), "+f"(c3)
                 : "r"(a0), "r"(a1), "r"(a2), "r"(a3), "r"(b0), "r"(b1));
}

// acquire-poll until counter >= target
__device__ __forceinline__ void waitcnt(const unsigned* p, unsigned target)
{
    unsigned v;
    do {
        asm volatile("ld.global.acquire.gpu.u32 %0, [%1];"
                     : "=r"(v) : "l"(p) : "memory");
    } while (v < target);
}

// ---------------- prep kernels ----------------
// x (B,T,IDIM) fp32 -> g_x16 (T,B,IDIM) fp16
__global__ void cvt_x(const float* __restrict__ x)
{
    size_t i = (size_t)blockIdx.x * blockDim.x + threadIdx.x;
    size_t n2 = (size_t)B_ * T_ * IDIM / 2;
    if (i >= n2) return;
    size_t e = i * 2;
    int b = (int)(e / (T_ * IDIM));
    int rem = (int)(e - (size_t)b * (T_ * IDIM));
    int t = rem / IDIM;
    int c = rem - t * IDIM;
    float2 v = ((const float2*)x)[i];
    ((__half2*)g_x16)[(((size_t)t * B_ + b) * IDIM + c) / 2] = __floats2half2_rn(v.x, v.y);
}

__global__ void build_w16(const float* __restrict__ W1, const float* __restrict__ W2,
                          const float* __restrict__ Wa, const float* __restrict__ Wb,
                          const float* __restrict__ mask,
                          const float* __restrict__ b1, const float* __restrict__ b2,
                          const float* __restrict__ ba, const float* __restrict__ bb,
                          __half* __restrict__ Wc, float* __restrict__ bc,
                          int n, int Korig, int k1real, int k1pad, int KP, int NP)
{
    int idx = blockIdx.x * blockDim.x + threadIdx.x;
    if (idx < NP * KP) {
        int row = idx / KP, kp = idx - row * KP;
        float v = 0.f;
        if (row < 4 * n) {
            int kk = -1;
            if (kp < k1real) kk = kp;
            else if (kp >= k1pad && kp < k1pad + (Korig - k1real)) kk = k1real + (kp - k1pad);
            if (kk >= 0) {
                int j = row >> 2, g = row & 3;
                if (g == 0)      v = W1[(size_t)j * Korig + kk] * mask[(size_t)j * Korig + kk];
                else if (g == 1) v = W2[(size_t)j * Korig + kk] * mask[(size_t)j * Korig + kk];
                else if (g == 2) v = Wa[(size_t)j * Korig + kk];
                else             v = Wb[(size_t)j * Korig + kk];
            }
        }
        Wc[idx] = __float2half_rn(v);
    }
    if (idx < NP) {
        float v = 0.f;
        if (idx < 4 * n) {
            int j = idx >> 2, g = idx & 3;
            v = (g == 0) ? b1[j] : (g == 1) ? b2[j] : (g == 2) ? ba[j] : bb[j];
        }
        bc[idx] = v;
    }
}

__global__ void zero_h16()
{
    int i = blockIdx.x * blockDim.x + threadIdx.x;
    __half2 z = __half2half2(__float2half(0.f));
    if (i < 2 * B_ * LH0 / 2) ((__half2*)g_h16_0)[i] = z;
    if (i < 2 * B_ * LH1 / 2) ((__half2*)g_h16_1)[i] = z;
    if (i < 2 * B_ * LH2 / 2) ((__half2*)g_h16_2)[i] = z;
}

__global__ void fill_h16(const float* __restrict__ h0in)
{
    int idx = blockIdx.x * blockDim.x + threadIdx.x;
    if (idx >= B_ * UNITS) return;
    int b = idx / UNITS, c = idx - b * UNITS;
    __half v = __float2half_rn(h0in[idx]);
    if (c < N0)           g_h16_0[0][b * LH0 + c] = v;
    else if (c < N0 + N1) g_h16_1[0][b * LH1 + (c - N0)] = v;
    else                  g_h16_2[0][b * LH2 + (c - N0 - N1)] = v;
}

__global__ void write_hn(float* __restrict__ out)
{
    int idx = blockIdx.x * blockDim.x + threadIdx.x;
    if (idx >= B_ * UNITS) return;
    int b = idx / UNITS, c = idx - b * UNITS;
    float v;
    if (c < N0)           v = g_h32_0[b * N0 + c];
    else if (c < N0 + N1) v = g_h32_1[b * N1 + (c - N0)];
    else                  v = g_h32_2[b * N2 + (c - N0 - N1)];
    out[idx] = v;
}

__global__ void reset_cnt()
{
    int i = blockIdx.x * blockDim.x + threadIdx.x;
    if (i < 3 * 4 * T_) ((unsigned*)g_cnt)[i] = 0u;
}

// ---------------- A segment base per (layer,t,64-chunk j), m0 applied ----------------
__device__ __forceinline__ const __half* a_base64(int layer, int t, int j, int m0, int& stride)
{
    if (layer == 0) {
        if (j < 8) { stride = IDIM; return g_x16 + ((size_t)t * B_ + m0) * IDIM + j * 64; }
        stride = LH0; return g_h16_0[t & 1] + (size_t)m0 * LH0 + (j - 8) * 64;
    } else if (layer == 1) {
        if (j < 9) { stride = LH0; return g_h16_0[1 - (t & 1)] + (size_t)m0 * LH0 + j * 64; }
        stride = LH1; return g_h16_1[t & 1] + (size_t)m0 * LH1 + (j - 9) * 64;
    } else {
        if (j < 6) { stride = LH1; return g_h16_1[1 - (t & 1)] + (size_t)m0 * LH1 + j * 64; }
        stride = LH2; return g_h16_2[t & 1] + (size_t)m0 * LH2 + (j - 6) * 64;
    }
}

// ---------------- one 128x128 tile (BK=64): fp16 ldmatrix/mma + fused CfC gate ----------------
__device__ void run_tile(int layer, int t, int m0, int n0, char* smbase)
{
    const __half* wbase; const float* bias; int KP, nkt;
    if (layer == 0)      { wbase = g_w0; bias = g_bc0; KP = KP0; nkt = KP0 / 64; }
    else if (layer == 1) { wbase = g_w1; bias = g_bc1; KP = KP1; nkt = KP1 / 64; }
    else                 { wbase = g_w2; bias = g_bc2; KP = KP2; nkt = KP2 / 64; }

    const uint32_t sm_u32 = s2u(smbase);
    const int tid  = threadIdx.x;
    const int lane = tid & 31;
    const int wid  = tid >> 5;
    const int wm   = wid & 1;        // 2 warps in M (64 rows each)
    const int wn   = wid >> 1;       // 4 warps in N (32 cols each)

    float acc[4][4][4];
    #pragma unroll
    for (int mt = 0; mt < 4; mt++)
        #pragma unroll
        for (int nt = 0; nt < 4; nt++)
            #pragma unroll
            for (int i = 0; i < 4; i++) acc[mt][nt][i] = 0.f;

    // fill one 64-wide stage: A 128x64 + B 128x64, 144B-padded rows
    auto fill = [&](int j) {
        int s = j & 1;
        uint32_t a_s = sm_u32 + s * STAGEB;
        uint32_t b_s = sm_u32 + 2 * STAGEB + s * STAGEB;
        int astr; const __half* ab = a_base64(layer, t, j, m0, astr);
        const __half* wb = wbase + (size_t)n0 * KP + j * 64;
        #pragma unroll
        for (int i = 0; i < 4; i++) {
            int u = tid + i * 256;
            int r = u >> 3, q = u & 7;
            cpa16(a_s + r * ROWB + q * 16, ab + (size_t)r * astr + q * 8);
            cpa16(b_s + r * ROWB + q * 16, wb + (size_t)r * KP + q * 8);
        }
        CP_COMMIT();
    };

    fill(0);

    for (int kt = 0; kt < nkt; kt++) {
        CP_WAIT0();           // stage kt complete (only outstanding group)
        __syncthreads();      // publish stage + retire previous compute
        if (kt + 1 < nkt) fill(kt + 1);   // overlaps with compute below

        int buf = kt & 1;
        uint32_t a_s = sm_u32 + buf * STAGEB;
        uint32_t b_s = sm_u32 + 2 * STAGEB + buf * STAGEB;

        #pragma unroll
        for (int ks = 0; ks < 64; ks += 16) {
            uint32_t af[4][4], bf[4][2];
            #pragma unroll
            for (int mt = 0; mt < 4; mt++) {
                int row = wm * 64 + mt * 16 + (lane & 15);
                uint32_t addr = a_s + row * ROWB + ks * 2 + (lane >> 4) * 16;
                ldsm_x4(af[mt][0], af[mt][1], af[mt][2], af[mt][3], addr);
            }
            #pragma unroll
            for (int j = 0; j < 2; j++) {
                int q = lane >> 3;
                int row = wn * 32 + 16 * j + (q >> 1) * 8 + (lane & 7);
                uint32_t addr = b_s + row * ROWB + (ks + (q & 1) * 8) * 2;
                ldsm_x4(bf[2 * j][0], bf[2 * j][1], bf[2 * j + 1][0], bf[2 * j + 1][1], addr);
            }
            #pragma unroll
            for (int mt = 0; mt < 4; mt++)
                #pragma unroll
                for (int nt = 0; nt < 4; nt++)
                    mma_f16(acc[mt][nt][0], acc[mt][nt][1], acc[mt][nt][2], acc[mt][nt][3],
                            af[mt][0], af[mt][1], af[mt][2], af[mt][3],
                            bf[nt][0], bf[nt][1]);
        }
    }

    // ---- epilogue: stage C in smem (aliases stage buffers), then gate ----
    __syncthreads();
    float* Cs = (float*)smbase;   // [128][LDC]
    {
        int g = lane >> 2, tk = lane & 3;
        #pragma unroll
        for (int mt = 0; mt < 4; mt++) {
            int row = wm * 64 + mt * 16 + g;
            #pragma unroll
            for (int nt = 0; nt < 4; nt++) {
                int col = wn * 32 + nt * 8 + 2 * tk;
                Cs[row * LDC + col]           = acc[mt][nt][0];
                Cs[row * LDC + col + 1]       = acc[mt][nt][1];
                Cs[(row + 8) * LDC + col]     = acc[mt][nt][2];
                Cs[(row + 8) * LDC + col + 1] = acc[mt][nt][3];
            }
        }
    }
    __syncthreads();

    // outputs
    __half* h16; int ldh;
    float *f1 = nullptr, *f2 = nullptr; int ldf1 = 0, ldf2 = 0, n1 = 0, nr2 = 0;
    int wp = 1 - (t & 1);
    bool last = (t == T_ - 1);
    if (layer == 0) {
        h16 = g_h16_0[wp]; ldh = LH0;
        if (last) { f1 = g_h32_0; ldf1 = N0; n1 = N0; }
    } else if (layer == 1) {
        h16 = g_h16_1[wp]; ldh = LH1;
        if (last) { f1 = g_h32_1; ldf1 = N1; n1 = N1; }
    } else {
        h16 = g_h16_2[wp]; ldh = LH2;
        f1 = g_motor + (size_t)t * OUT_; ldf1 = T_ * OUT_; n1 = N2;
        if (last) { f2 = g_h32_2; ldf2 = N2; nr2 = N2; }
    }

    {
        int ul = tid & 31;                 // 32 units per 128-col tile
        int u  = (n0 >> 2) + ul;
        float4 bb = *(const float4*)(bias + 4 * u);
        #pragma unroll
        for (int r = 0; r < 16; r++) {
            int row = (tid >> 5) + 8 * r;
            float4 v = *(const float4*)(Cs + row * LDC + 4 * ul);
            float ff1 = tanhf(v.x + bb.x);
            float ff2 = tanhf(v.y + bb.y);
            float s   = (v.z + bb.z) + (v.w + bb.w);
            float tg  = 1.f / (1.f + __expf(-s));
            float h   = ff1 + tg * (ff2 - ff1);
            size_t grow = (size_t)(m0 + row);
            h16[grow * ldh + u] = __float2half_rn(h);
            if (f1 && u < n1)  f1[grow * ldf1 + u] = h;
            if (f2 && u < nr2) f2[grow * ldf2 + u] = h;
        }
    }
    __syncthreads();   // all epilogue stores done before flag publish / smem reuse
}

// ---------------- persistent dataflow kernel (no grid barrier) ----------------
// CTA groups: L0 tiles (68) rotate over 85 CTAs, L1 (48) over 53, L2 (16) over 10.
// Dependencies (per (layer, mrow, t) counters):
//   L0(t): cnt0[mrow][t-1]==17 (input h0)         ; cnt1[mrow][t-2]==12 (WAR on h0 buf)
//   L1(t): cnt0[mrow][t]==17   ; cnt1[mrow][t-1]==12 ; cnt2[mrow][t-2]==4 (WAR on h1 buf)
//   L2(t): cnt1[mrow][t]==12   ; cnt2[mrow][t-1]==4
__global__ __launch_bounds__(256, 1)
void rnn_f16()
{
    extern __shared__ char smraw[];
    char* smbase = (char*)(((uintptr_t)smraw + 127) & ~(uintptr_t)127);
    const int bid = blockIdx.x;

    int layer, NT, NC, c;
    if (bid < 85)       { layer = 0; NT = 68; NC = 85; c = bid; }
    else if (bid < 138) { layer = 1; NT = 48; NC = 53; c = bid - 85; }
    else                { layer = 2; NT = 16; NC = 10; c = bid - 138; }

    for (int g = c; g < T_ * NT; g += NC) {
        int t  = g / NT;
        int ti = g - t * NT;
        int mrow = ti & 3, ncol = ti >> 2;

        if (threadIdx.x == 0) {
            if (layer == 0) {
                if (t >= 1) waitcnt(&g_cnt[0][mrow][t - 1], 17u);
                if (t >= 2) waitcnt(&g_cnt[1][mrow][t - 2], 12u);
            } else if (layer == 1) {
                waitcnt(&g_cnt[0][mrow][t], 17u);
                if (t >= 1) waitcnt(&g_cnt[1][mrow][t - 1], 12u);
                if (t >= 2) waitcnt(&g_cnt[2][mrow][t - 2], 4u);
            } else {
                waitcnt(&g_cnt[1][mrow][t], 12u);
                if (t >= 1) waitcnt(&g_cnt[2][mrow][t - 1], 4u);
            }
        }
        __syncthreads();

        run_tile(layer, t, mrow * 128, ncol * 128, smbase);

        if (threadIdx.x == 0) {
            __threadfence();
            atomicAdd(&g_cnt[layer][mrow][t], 1u);
        }
    }
}

// ================= tf32 path for the final FC (verified) =================
#define BMF 128
#define BKF 32
#define LDKF 36
#define LDCF 132
#define SMEM_FC (4*BMF*LDKF*4)

__device__ __forceinline__ float f2tf32(float f) {
    unsigned r;
    asm("cvt.rna.tf32.f32 %0, %1;" : "=r"(r) : "f"(f));
    return __uint_as_float(r);
}
__device__ __forceinline__ void mma_tf32(float& c0, float& c1, float& c2, float& c3,
                                         unsigned a0, unsigned a1, unsigned a2, unsigned a3,
                                         unsigned b0, unsigned b1)
{
    asm volatile("mma.sync.aligned.m16n8k8.row.col.f32.tf32.tf32.f32 "
                 "{%0,%1,%2,%3}, {%4,%5,%6,%7}, {%8,%9}, {%0,%1,%2,%3};"
                 : "+f"(c0), "+f"(c1), "+f"(c2), "+f"(c3)
                 : "r"(a0), "r"(a1), "r"(a2), "r"(a3), "r"(b0), "r"(b1));
}

__global__ __launch_bounds__(256)
void fc_kernel(float* __restrict__ pred, const float* __restrict__ Wfc,
               const float* __restrict__ bfc)
{
    extern __shared__ float sm[];
    float* As = sm;
    float* Bs = sm + 2 * BMF * LDKF;

    const float* A = g_motor;
    const int Ktot = OUT_;
    const int Nout = OUT_;

    const int tid  = threadIdx.x;
    const int lane = tid & 31;
    const int g    = lane >> 2;
    const int tk   = lane & 3;
    const int wid  = tid >> 5;
    const int wm   = wid & 1;
    const int wn   = wid >> 1;
    const int m0   = blockIdx.x * BMF;

    const int lK  = tid & 31;
    const int arb = tid >> 5;
    const int bkg = (tid & 7) * 4;
    const int bnb = tid >> 3;

    float acc[4][4][4];
    #pragma unroll
    for (int mt = 0; mt < 4; mt++)
        #pragma unroll
        for (int nt = 0; nt < 4; nt++)
            #pragma unroll
            for (int i = 0; i < 4; i++) acc[mt][nt][i] = 0.f;

    const int nkt = 128 / BKF;
    float areg[16]; float4 breg[4];

    auto ldg = [&](int kt) {
        int k = kt * BKF + lK;
        #pragma unroll
        for (int r = 0; r < 16; r++)
            areg[r] = A[(size_t)(m0 + arb + r * 8) * Ktot + k];
        int kb = kt * BKF + bkg;
        #pragma unroll
        for (int r = 0; r < 4; r++)
            breg[r] = *(const float4*)(Wfc + (size_t)(bnb + r * 32) * Ktot + kb);
    };
    auto sts = [&](int buf) {
        float* a = As + buf * BMF * LDKF;
        float* b = Bs + buf * BMF * LDKF;
        #pragma unroll
        for (int r = 0; r < 16; r++) a[(arb + r * 8) * LDKF + lK] = f2tf32(areg[r]);
        #pragma unroll
        for (int r = 0; r < 4; r++) {
            float4 v = breg[r];
            v.x = f2tf32(v.x); v.y = f2tf32(v.y); v.z = f2tf32(v.z); v.w = f2tf32(v.w);
            *(float4*)(b + (bnb + r * 32) * LDKF + bkg) = v;
        }
    };

    ldg(0); sts(0); __syncthreads();

    for (int kt = 0; kt < nkt; kt++) {
        if (kt + 1 < nkt) ldg(kt + 1);
        const float* a = As + (kt & 1) * BMF * LDKF;
        const float* b = Bs + (kt & 1) * BMF * LDKF;
        #pragma unroll
        for (int ks = 0; ks < BKF; ks += 8) {
            unsigned af[4][4], bf[4][2];
            #pragma unroll
            for (int mt = 0; mt < 4; mt++) {
                int row = wm * 64 + mt * 16 + g;
                af[mt][0] = __float_as_uint(a[row * LDKF + ks + tk]);
                af[mt][1] = __float_as_uint(a[(row + 8) * LDKF + ks + tk]);
                af[mt][2] = __float_as_uint(a[row * LDKF + ks + tk + 4]);
                af[mt][3] = __float_as_uint(a[(row + 8) * LDKF + ks + tk + 4]);
            }
            #pragma unroll
            for (int nt = 0; nt < 4; nt++) {
                int n = wn * 32 + nt * 8 + g;
                bf[nt][0] = __float_as_uint(b[n * LDKF + ks + tk]);
                bf[nt][1] = __float_as_uint(b[n * LDKF + ks + tk + 4]);
            }
            #pragma unroll
            for (int mt = 0; mt < 4; mt++)
                #pragma unroll
                for (int nt = 0; nt < 4; nt++)
                    mma_tf32(acc[mt][nt][0], acc[mt][nt][1], acc[mt][nt][2], acc[mt][nt][3],
                             af[mt][0], af[mt][1], af[mt][2], af[mt][3],
                             bf[nt][0], bf[nt][1]);
        }
        if (kt + 1 < nkt) { sts((kt + 1) & 1); __syncthreads(); }
    }

    __syncthreads();
    float* Cs = sm;
    #pragma unroll
    for (int mt = 0; mt < 4; mt++) {
        int row = wm * 64 + mt * 16 + g;
        #pragma unroll
        for (int nt = 0; nt < 4; nt++) {
            int col = wn * 32 + nt * 8 + 2 * tk;
            Cs[row * LDCF + col]           = acc[mt][nt][0];
            Cs[row * LDCF + col + 1]       = acc[mt][nt][1];
            Cs[(row + 8) * LDCF + col]     = acc[mt][nt][2];
            Cs[(row + 8) * LDCF + col + 1] = acc[mt][nt][3];
        }
    }
    __syncthreads();

    int ul  = tid & 31;
    int col = 4 * ul;
    float4 bb = *(const float4*)(bfc + col);
    #pragma unroll
    for (int r = 0; r < 16; r++) {
        int row = (tid >> 5) + 8 * r;
        float4 v = *(const float4*)(Cs + row * LDCF + col);
        v.x += bb.x; v.y += bb.y; v.z += bb.z; v.w += bb.w;
        *(float4*)(pred + (size_t)(m0 + row) * Nout + col) = v;
    }
}

// ---------------- launcher ----------------
extern "C" void kernel_launch(void* const* d_in, const int* in_sizes, int n_in,
                              void* d_out, int out_size)
{
    (void)in_sizes; (void)n_in; (void)out_size;
    const float* x    = (const float*)d_in[0];
    const float* h0in = (const float*)d_in[1];
    const float* mask[3]  = { (const float*)d_in[2],  (const float*)d_in[11], (const float*)d_in[20] };
    const float* Wff1[3]  = { (const float*)d_in[3],  (const float*)d_in[12], (const float*)d_in[21] };
    const float* Wff2[3]  = { (const float*)d_in[4],  (const float*)d_in[13], (const float*)d_in[22] };
    const float* Wta[3]   = { (const float*)d_in[5],  (const float*)d_in[14], (const float*)d_in[23] };
    const float* Wtb[3]   = { (const float*)d_in[6],  (const float*)d_in[15], (const float*)d_in[24] };
    const float* bff1[3]  = { (const float*)d_in[7],  (const float*)d_in[16], (const float*)d_in[25] };
    const float* bff2[3]  = { (const float*)d_in[8],  (const float*)d_in[17], (const float*)d_in[26] };
    const float* bta[3]   = { (const float*)d_in[9],  (const float*)d_in[18], (const float*)d_in[27] };
    const float* btb[3]   = { (const float*)d_in[10], (const float*)d_in[19], (const float*)d_in[28] };
    const float* Wfc = (const float*)d_in[29];
    const float* bfc = (const float*)d_in[30];

    float* out  = (float*)d_out;
    float* pred = out;
    float* hn   = out + (size_t)B_ * T_ * OUT_;

    cudaFuncSetAttribute(rnn_f16,   cudaFuncAttributeMaxDynamicSharedMemorySize, SMEM_DYN);
    cudaFuncSetAttribute(fc_kernel, cudaFuncAttributeMaxDynamicSharedMemorySize, SMEM_FC);

    __half* dW16[3]; float* dbc[3];
    cudaGetSymbolAddress((void**)&dW16[0], g_w0);
    cudaGetSymbolAddress((void**)&dW16[1], g_w1);
    cudaGetSymbolAddress((void**)&dW16[2], g_w2);
    cudaGetSymbolAddress((void**)&dbc[0], g_bc0);
    cudaGetSymbolAddress((void**)&dbc[1], g_bc1);
    cudaGetSymbolAddress((void**)&dbc[2], g_bc2);

    {
        size_t n2 = (size_t)B_ * T_ * IDIM / 2;
        cvt_x<<<(unsigned)((n2 + 255) / 256), 256>>>(x);
    }
    {
        int tot = NP0 * KP0;
        build_w16<<<(tot + 255) / 256, 256>>>(Wff1[0], Wff2[0], Wta[0], Wtb[0], mask[0],
                                              bff1[0], bff2[0], bta[0], btb[0],
                                              dW16[0], dbc[0], N0, 1050, 512, 512, KP0, NP0);
    }
    {
        int tot = NP1 * KP1;
        build_w16<<<(tot + 255) / 256, 256>>>(Wff1[1], Wff2[1], Wta[1], Wtb[1], mask[1],
                                              bff1[1], bff2[1], bta[1], btb[1],
                                              dW16[1], dbc[1], N1, 896, 538, 576, KP1, NP1);
    }
    {
        int tot = NP2 * KP2;
        build_w16<<<(tot + 255) / 256, 256>>>(Wff1[2], Wff2[2], Wta[2], Wtb[2], mask[2],
                                              bff1[2], bff2[2], bta[2], btb[2],
                                              dW16[2], dbc[2], N2, 486, 358, 384, KP2, NP2);
    }
    zero_h16<<<(2 * B_ * LH0 / 2 + 255) / 256, 256>>>();
    fill_h16<<<(B_ * UNITS + 255) / 256, 256>>>(h0in);
    reset_cnt<<<(3 * 4 * T_ + 255) / 256, 256>>>();

    rnn_f16<<<NCTA, 256, SMEM_DYN>>>();

    fc_kernel<<<(B_ * T_) / BMF, 256, SMEM_FC>>>(pred, Wfc, bfc);
    write_hn<<<(B_ * UNITS + 255) / 256, 256>>>(hn);
}

// round 15
// speedup vs baseline: 1.1179x; 1.1179x over previous
#include <cuda_runtime.h>
#include <cuda_fp16.h>
#include <math.h>
#include <stdint.h>

// ---------------- problem dims ----------------
#define B_    512
#define T_    128
#define IDIM  512
#define N0    538
#define N1    358
#define N2    128
#define OUT_  128
#define UNITS 1024

// padded fp16 layouts (all K segments multiples of 64)
#define NP0   2176      // 4*538=2152 -> 17*128
#define KP0   1088      // [x 512 | h0 538->576]
#define NP1   1536      // 4*358=1432 -> 12*128
#define KP1   960       // [h0 576 | h1 358->384]
#define NP2   512       // 4*128
#define KP2   512       // [h1 384 | h2 128]
#define LH0   576
#define LH1   384
#define LH2   128

#define NCTA  132       // 68 L0 + 48 L1 + 16 L2

// tile: CTA 128x128, BK=64 per main-loop step
#define ROWB     144                 // stage row stride in bytes (128 data + 16 pad)
#define STAGEB   (128*ROWB)          // 18432 B per matrix per stage
#define LDC      132                 // C staging row stride (floats)
#define SMEM_DYN (4*STAGEB + 128)    // 73856 B; Cs (128*132*4 = 67584 B) aliases

// ---------------- device globals ----------------
__device__ __align__(16) __half g_x16[(size_t)B_ * T_ * IDIM];   // transposed: (T, B, IDIM)
__device__ __align__(16) __half g_w0[(size_t)NP0 * KP0];
__device__ __align__(16) __half g_w1[(size_t)NP1 * KP1];
__device__ __align__(16) __half g_w2[(size_t)NP2 * KP2];
__device__ __align__(16) float  g_bc0[NP0];
__device__ __align__(16) float  g_bc1[NP1];
__device__ __align__(16) float  g_bc2[NP2];
__device__ __align__(16) __half g_h16_0[2][B_ * LH0];
__device__ __align__(16) __half g_h16_1[2][B_ * LH1];
__device__ __align__(16) __half g_h16_2[2][B_ * LH2];
__device__ __align__(16) float  g_h32_0[B_ * N0];
__device__ __align__(16) float  g_h32_1[B_ * N1];
__device__ __align__(16) float  g_h32_2[B_ * N2];
__device__ __align__(16) float  g_motor[(size_t)B_ * T_ * OUT_];
__device__ unsigned g_bar_count;
__device__ unsigned g_bar_release;

// ---------------- PTX helpers ----------------
__device__ __forceinline__ uint32_t s2u(const void* p) {
    return (uint32_t)__cvta_generic_to_shared(p);
}
__device__ __forceinline__ void cpa16(uint32_t dst, const void* src) {
    asm volatile("cp.async.cg.shared.global [%0], [%1], 16;"
                 :: "r"(dst), "l"(src) : "memory");
}
#define CP_COMMIT() asm volatile("cp.async.commit_group;" ::: "memory")
#define CP_WAIT0()  asm volatile("cp.async.wait_group 0;" ::: "memory")

__device__ __forceinline__ void ldsm_x4(uint32_t& r0, uint32_t& r1, uint32_t& r2, uint32_t& r3,
                                        uint32_t addr)
{
    asm volatile("ldmatrix.sync.aligned.m8n8.x4.shared.b16 {%0,%1,%2,%3}, [%4];"
                 : "=r"(r0), "=r"(r1), "=r"(r2), "=r"(r3) : "r"(addr));
}
__device__ __forceinline__ void mma_f16(float& c0, float& c1, float& c2, float& c3,
                                        uint32_t a0, uint32_t a1, uint32_t a2, uint32_t a3,
                                        uint32_t b0, uint32_t b1)
{
    asm volatile("mma.sync.aligned.m16n8k16.row.col.f32.f16.f16.f32 "
                 "{%0,%1,%2,%3}, {%4,%5,%6,%7}, {%8,%9}, {%0,%1,%2,%3};"
                 : "+f"(c0), "+f"(c1), "+f"(c2), "+f"(c3)
                 : "r"(a0), "r"(a1), "r"(a2), "r"(a3), "r"(b0), "r"(b1));
}

// ---------------- prep kernels (merged to position rnn_f16 at launch #4) ----------------
// x (B,T,IDIM) fp32 -> g_x16 (T,B,IDIM) fp16            [launch 1]
__global__ void cvt_x(const float* __restrict__ x)
{
    size_t i = (size_t)blockIdx.x * blockDim.x + threadIdx.x;
    size_t n2 = (size_t)B_ * T_ * IDIM / 2;
    if (i >= n2) return;
    size_t e = i * 2;
    int b = (int)(e / (T_ * IDIM));
    int rem = (int)(e - (size_t)b * (T_ * IDIM));
    int t = rem / IDIM;
    int c = rem - t * IDIM;
    float2 v = ((const float2*)x)[i];
    ((__half2*)g_x16)[(((size_t)t * B_ + b) * IDIM + c) / 2] = __floats2half2_rn(v.x, v.y);
}

__device__ __forceinline__ void build_one(
    int idx,
    const float* __restrict__ W1, const float* __restrict__ W2,
    const float* __restrict__ Wa, const float* __restrict__ Wb,
    const float* __restrict__ mask,
    const float* __restrict__ b1, const float* __restrict__ b2,
    const float* __restrict__ ba, const float* __restrict__ bb,
    __half* __restrict__ Wc, float* __restrict__ bc,
    int n, int Korig, int k1real, int k1pad, int KP, int NP)
{
    if (idx < NP * KP) {
        int row = idx / KP, kp = idx - row * KP;
        float v = 0.f;
        if (row < 4 * n) {
            int kk = -1;
            if (kp < k1real) kk = kp;
            else if (kp >= k1pad && kp < k1pad + (Korig - k1real)) kk = k1real + (kp - k1pad);
            if (kk >= 0) {
                int j = row >> 2, g = row & 3;
                if (g == 0)      v = W1[(size_t)j * Korig + kk] * mask[(size_t)j * Korig + kk];
                else if (g == 1) v = W2[(size_t)j * Korig + kk] * mask[(size_t)j * Korig + kk];
                else if (g == 2) v = Wa[(size_t)j * Korig + kk];
                else             v = Wb[(size_t)j * Korig + kk];
            }
        }
        Wc[idx] = __float2half_rn(v);
    }
    if (idx < NP) {
        float v = 0.f;
        if (idx < 4 * n) {
            int j = idx >> 2, g = idx & 3;
            v = (g == 0) ? b1[j] : (g == 1) ? b2[j] : (g == 2) ? ba[j] : bb[j];
        }
        bc[idx] = v;
    }
}

#define GB0 9248    // NP0*KP0/256
#define GB1 5760    // NP1*KP1/256
#define GB2 1024    // NP2*KP2/256

// single kernel building all 3 layers                    [launch 2]
__global__ void build_all(
    const float* W1_0, const float* W2_0, const float* Wa_0, const float* Wb_0,
    const float* mk_0, const float* b1_0, const float* b2_0, const float* ba_0, const float* bb_0,
    const float* W1_1, const float* W2_1, const float* Wa_1, const float* Wb_1,
    const float* mk_1, const float* b1_1, const float* b2_1, const float* ba_1, const float* bb_1,
    const float* W1_2, const float* W2_2, const float* Wa_2, const float* Wb_2,
    const float* mk_2, const float* b1_2, const float* b2_2, const float* ba_2, const float* bb_2)
{
    int blk = blockIdx.x;
    if (blk < GB0) {
        int idx = blk * 256 + threadIdx.x;
        build_one(idx, W1_0, W2_0, Wa_0, Wb_0, mk_0, b1_0, b2_0, ba_0, bb_0,
                  g_w0, g_bc0, N0, 1050, 512, 512, KP0, NP0);
    } else if (blk < GB0 + GB1) {
        int idx = (blk - GB0) * 256 + threadIdx.x;
        build_one(idx, W1_1, W2_1, Wa_1, Wb_1, mk_1, b1_1, b2_1, ba_1, bb_1,
                  g_w1, g_bc1, N1, 896, 538, 576, KP1, NP1);
    } else {
        int idx = (blk - GB0 - GB1) * 256 + threadIdx.x;
        build_one(idx, W1_2, W2_2, Wa_2, Wb_2, mk_2, b1_2, b2_2, ba_2, bb_2,
                  g_w2, g_bc2, N2, 486, 358, 384, KP2, NP2);
    }
}

// init h16 buffers (both ping-pong bufs: buf0 = h0 values + pad, buf1 = 0),
// reset barrier state                                     [launch 3]
#define IH0 (2 * B_ * LH0)
#define IH1 (2 * B_ * LH1)
#define IH2 (2 * B_ * LH2)
__global__ void init_all(const float* __restrict__ h0in)
{
    int idx = blockIdx.x * blockDim.x + threadIdx.x;
    if (idx == 0) { g_bar_count = 0; g_bar_release = 0; }

    int r = idx;
    if (r < IH0) {
        int buf = r / (B_ * LH0); int e = r - buf * (B_ * LH0);
        int b = e / LH0, c = e - b * LH0;
        float v = (buf == 0 && c < N0) ? h0in[b * UNITS + c] : 0.f;
        g_h16_0[buf][e] = __float2half_rn(v);
        return;
    }
    r -= IH0;
    if (r < IH1) {
        int buf = r / (B_ * LH1); int e = r - buf * (B_ * LH1);
        int b = e / LH1, c = e - b * LH1;
        float v = (buf == 0 && c < N1) ? h0in[b * UNITS + N0 + c] : 0.f;
        g_h16_1[buf][e] = __float2half_rn(v);
        return;
    }
    r -= IH1;
    if (r < IH2) {
        int buf = r / (B_ * LH2); int e = r - buf * (B_ * LH2);
        int b = e / LH2, c = e - b * LH2;
        float v = (buf == 0) ? h0in[b * UNITS + N0 + N1 + c] : 0.f;
        g_h16_2[buf][e] = __float2half_rn(v);
    }
}

__global__ void write_hn(float* __restrict__ out)
{
    int idx = blockIdx.x * blockDim.x + threadIdx.x;
    if (idx >= B_ * UNITS) return;
    int b = idx / UNITS, c = idx - b * UNITS;
    float v;
    if (c < N0)           v = g_h32_0[b * N0 + c];
    else if (c < N0 + N1) v = g_h32_1[b * N1 + (c - N0)];
    else                  v = g_h32_2[b * N2 + (c - N0 - N1)];
    out[idx] = v;
}

// ---------------- grid barrier ----------------
__device__ __forceinline__ void grid_bar(int epoch)
{
    __syncthreads();
    if (threadIdx.x == 0) {
        __threadfence();
        unsigned a = atomicAdd(&g_bar_count, 1u) + 1u;
        if (a == (unsigned)(NCTA * epoch)) {
            asm volatile("st.global.release.gpu.u32 [%0], %1;"
                         :: "l"(&g_bar_release), "r"((unsigned)epoch) : "memory");
        } else {
            unsigned r;
            do {
                asm volatile("ld.global.acquire.gpu.u32 %0, [%1];"
                             : "=r"(r) : "l"(&g_bar_release) : "memory");
            } while (r < (unsigned)epoch);
        }
    }
    __syncthreads();
}

// ---------------- A segment base per (layer,t,64-chunk j), m0 applied ----------------
__device__ __forceinline__ const __half* a_base64(int layer, int t, int j, int m0, int& stride)
{
    if (layer == 0) {
        if (j < 8) { stride = IDIM; return g_x16 + ((size_t)t * B_ + m0) * IDIM + j * 64; }
        stride = LH0; return g_h16_0[t & 1] + (size_t)m0 * LH0 + (j - 8) * 64;
    } else if (layer == 1) {
        if (j < 9) { stride = LH0; return g_h16_0[1 - (t & 1)] + (size_t)m0 * LH0 + j * 64; }
        stride = LH1; return g_h16_1[t & 1] + (size_t)m0 * LH1 + (j - 9) * 64;
    } else {
        if (j < 6) { stride = LH1; return g_h16_1[1 - (t & 1)] + (size_t)m0 * LH1 + j * 64; }
        stride = LH2; return g_h16_2[t & 1] + (size_t)m0 * LH2 + (j - 6) * 64;
    }
}

// prefetch stage 0 of an L0 tile for step t (reads only x — dependency-free)
__device__ __forceinline__ void prefetch_l0_s0(int t, int m0, int n0, uint32_t sm_u32)
{
    uint32_t a_s = sm_u32;                 // buf 0
    uint32_t b_s = sm_u32 + 2 * STAGEB;    // buf 0
    const __half* ab = g_x16 + ((size_t)t * B_ + m0) * IDIM;   // j = 0
    const __half* wb = g_w0 + (size_t)n0 * KP0;
    int tid = threadIdx.x;
    #pragma unroll
    for (int i = 0; i < 4; i++) {
        int u = tid + i * 256;
        int r = u >> 3, q = u & 7;
        cpa16(a_s + r * ROWB + q * 16, ab + (size_t)r * IDIM + q * 8);
        cpa16(b_s + r * ROWB + q * 16, wb + (size_t)r * KP0 + q * 8);
    }
    CP_COMMIT();
}

// ---------------- one 128x128 tile (BK=64): fp16 ldmatrix/mma + fused CfC gate ----------------
__device__ void run_tile(int layer, int t, int m0, int n0, char* smbase, bool pre)
{
    const __half* wbase; const float* bias; int KP, nkt;
    if (layer == 0)      { wbase = g_w0; bias = g_bc0; KP = KP0; nkt = KP0 / 64; }
    else if (layer == 1) { wbase = g_w1; bias = g_bc1; KP = KP1; nkt = KP1 / 64; }
    else                 { wbase = g_w2; bias = g_bc2; KP = KP2; nkt = KP2 / 64; }

    const uint32_t sm_u32 = s2u(smbase);
    const int tid  = threadIdx.x;
    const int lane = tid & 31;
    const int wid  = tid >> 5;
    const int wm   = wid & 1;        // 2 warps in M (64 rows each)
    const int wn   = wid >> 1;       // 4 warps in N (32 cols each)

    float acc[4][4][4];
    #pragma unroll
    for (int mt = 0; mt < 4; mt++)
        #pragma unroll
        for (int nt = 0; nt < 4; nt++)
            #pragma unroll
            for (int i = 0; i < 4; i++) acc[mt][nt][i] = 0.f;

    // fill one 64-wide stage: A 128x64 + B 128x64, 144B-padded rows
    auto fill = [&](int j) {
        int s = j & 1;
        uint32_t a_s = sm_u32 + s * STAGEB;
        uint32_t b_s = sm_u32 + 2 * STAGEB + s * STAGEB;
        int astr; const __half* ab = a_base64(layer, t, j, m0, astr);
        const __half* wb = wbase + (size_t)n0 * KP + j * 64;
        #pragma unroll
        for (int i = 0; i < 4; i++) {
            int u = tid + i * 256;
            int r = u >> 3, q = u & 7;
            cpa16(a_s + r * ROWB + q * 16, ab + (size_t)r * astr + q * 8);
            cpa16(b_s + r * ROWB + q * 16, wb + (size_t)r * KP + q * 8);
        }
        CP_COMMIT();
    };

    if (!pre) fill(0);

    for (int kt = 0; kt < nkt; kt++) {
        CP_WAIT0();           // stage kt complete (only outstanding group)
        __syncthreads();      // publish stage + retire previous compute
        if (kt + 1 < nkt) fill(kt + 1);   // overlaps with compute below

        int buf = kt & 1;
        uint32_t a_s = sm_u32 + buf * STAGEB;
        uint32_t b_s = sm_u32 + 2 * STAGEB + buf * STAGEB;

        #pragma unroll
        for (int ks = 0; ks < 64; ks += 16) {
            uint32_t af[4][4], bf[4][2];
            #pragma unroll
            for (int mt = 0; mt < 4; mt++) {
                int row = wm * 64 + mt * 16 + (lane & 15);
                uint32_t addr = a_s + row * ROWB + ks * 2 + (lane >> 4) * 16;
                ldsm_x4(af[mt][0], af[mt][1], af[mt][2], af[mt][3], addr);
            }
            #pragma unroll
            for (int j = 0; j < 2; j++) {
                int q = lane >> 3;
                int row = wn * 32 + 16 * j + (q >> 1) * 8 + (lane & 7);
                uint32_t addr = b_s + row * ROWB + (ks + (q & 1) * 8) * 2;
                ldsm_x4(bf[2 * j][0], bf[2 * j][1], bf[2 * j + 1][0], bf[2 * j + 1][1], addr);
            }
            #pragma unroll
            for (int mt = 0; mt < 4; mt++)
                #pragma unroll
                for (int nt = 0; nt < 4; nt++)
                    mma_f16(acc[mt][nt][0], acc[mt][nt][1], acc[mt][nt][2], acc[mt][nt][3],
                            af[mt][0], af[mt][1], af[mt][2], af[mt][3],
                            bf[nt][0], bf[nt][1]);
        }
    }

    // ---- epilogue: stage C in smem (aliases stage buffers), then gate ----
    __syncthreads();
    float* Cs = (float*)smbase;   // [128][LDC]
    {
        int g = lane >> 2, tk = lane & 3;
        #pragma unroll
        for (int mt = 0; mt < 4; mt++) {
            int row = wm * 64 + mt * 16 + g;
            #pragma unroll
            for (int nt = 0; nt < 4; nt++) {
                int col = wn * 32 + nt * 8 + 2 * tk;
                Cs[row * LDC + col]           = acc[mt][nt][0];
                Cs[row * LDC + col + 1]       = acc[mt][nt][1];
                Cs[(row + 8) * LDC + col]     = acc[mt][nt][2];
                Cs[(row + 8) * LDC + col + 1] = acc[mt][nt][3];
            }
        }
    }
    __syncthreads();

    // outputs
    __half* h16; int ldh;
    float *f1 = nullptr, *f2 = nullptr; int ldf1 = 0, ldf2 = 0, n1 = 0, nr2 = 0;
    int wp = 1 - (t & 1);
    bool last = (t == T_ - 1);
    if (layer == 0) {
        h16 = g_h16_0[wp]; ldh = LH0;
        if (last) { f1 = g_h32_0; ldf1 = N0; n1 = N0; }
    } else if (layer == 1) {
        h16 = g_h16_1[wp]; ldh = LH1;
        if (last) { f1 = g_h32_1; ldf1 = N1; n1 = N1; }
    } else {
        h16 = g_h16_2[wp]; ldh = LH2;
        f1 = g_motor + (size_t)t * OUT_; ldf1 = T_ * OUT_; n1 = N2;
        if (last) { f2 = g_h32_2; ldf2 = N2; nr2 = N2; }
    }

    {
        int ul = tid & 31;                 // 32 units per 128-col tile
        int u  = (n0 >> 2) + ul;
        float4 bb = *(const float4*)(bias + 4 * u);
        #pragma unroll
        for (int r = 0; r < 16; r++) {
            int row = (tid >> 5) + 8 * r;
            float4 v = *(const float4*)(Cs + row * LDC + 4 * ul);
            float ff1 = tanhf(v.x + bb.x);
            float ff2 = tanhf(v.y + bb.y);
            float s   = (v.z + bb.z) + (v.w + bb.w);
            float tg  = 1.f / (1.f + __expf(-s));
            float h   = ff1 + tg * (ff2 - ff1);
            size_t grow = (size_t)(m0 + row);
            h16[grow * ldh + u] = __float2half_rn(h);
            if (f1 && u < n1)  f1[grow * ldf1 + u] = h;
            if (f2 && u < nr2) f2[grow * ldf2 + u] = h;
        }
    }
    __syncthreads();   // all epilogue stores done before prefetch reuses smem
}

// ---------------- persistent wavefront kernel ----------------
// phase p: L0 step p, L1 step p-1, L2 step p-2; one grid barrier per phase.
// L0 CTAs prefetch next step's x-only stage 0 before the barrier.
__global__ __launch_bounds__(256, 1)
void rnn_f16()
{
    extern __shared__ char smraw[];
    char* smbase = (char*)(((uintptr_t)smraw + 127) & ~(uintptr_t)127);
    const uint32_t sm_u32 = s2u(smbase);
    const int bid = blockIdx.x;

    int layer, mrow, ncol;
    if (bid < 68)       { layer = 0; mrow = bid & 3; ncol = bid >> 2; }
    else if (bid < 116) { layer = 1; int b = bid - 68;  mrow = b & 3; ncol = b >> 2; }
    else                { layer = 2; int b = bid - 116; mrow = b & 3; ncol = b >> 2; }

    for (int p = 0; p < T_ + 2; p++) {
        int t = p - layer;
        if (t >= 0 && t < T_)
            run_tile(layer, t, mrow * 128, ncol * 128, smbase,
                     (layer == 0 && t > 0));
        if (layer == 0 && t + 1 < T_)
            prefetch_l0_s0(t + 1, mrow * 128, ncol * 128, sm_u32);
        grid_bar(p + 1);
    }
}

// ================= tf32 path for the final FC (verified) =================
#define BMF 128
#define BKF 32
#define LDKF 36
#define LDCF 132
#define SMEM_FC (4*BMF*LDKF*4)

__device__ __forceinline__ float f2tf32(float f) {
    unsigned r;
    asm("cvt.rna.tf32.f32 %0, %1;" : "=r"(r) : "f"(f));
    return __uint_as_float(r);
}
__device__ __forceinline__ void mma_tf32(float& c0, float& c1, float& c2, float& c3,
                                         unsigned a0, unsigned a1, unsigned a2, unsigned a3,
                                         unsigned b0, unsigned b1)
{
    asm volatile("mma.sync.aligned.m16n8k8.row.col.f32.tf32.tf32.f32 "
                 "{%0,%1,%2,%3}, {%4,%5,%6,%7}, {%8,%9}, {%0,%1,%2,%3};"
                 : "+f"(c0), "+f"(c1), "+f"(c2), "+f"(c3)
                 : "r"(a0), "r"(a1), "r"(a2), "r"(a3), "r"(b0), "r"(b1));
}

__global__ __launch_bounds__(256)
void fc_kernel(float* __restrict__ pred, const float* __restrict__ Wfc,
               const float* __restrict__ bfc)
{
    extern __shared__ float sm[];
    float* As = sm;
    float* Bs = sm + 2 * BMF * LDKF;

    const float* A = g_motor;
    const int Ktot = OUT_;
    const int Nout = OUT_;

    const int tid  = threadIdx.x;
    const int lane = tid & 31;
    const int g    = lane >> 2;
    const int tk   = lane & 3;
    const int wid  = tid >> 5;
    const int wm   = wid & 1;
    const int wn   = wid >> 1;
    const int m0   = blockIdx.x * BMF;

    const int lK  = tid & 31;
    const int arb = tid >> 5;
    const int bkg = (tid & 7) * 4;
    const int bnb = tid >> 3;

    float acc[4][4][4];
    #pragma unroll
    for (int mt = 0; mt < 4; mt++)
        #pragma unroll
        for (int nt = 0; nt < 4; nt++)
            #pragma unroll
            for (int i = 0; i < 4; i++) acc[mt][nt][i] = 0.f;

    const int nkt = 128 / BKF;
    float areg[16]; float4 breg[4];

    auto ldg = [&](int kt) {
        int k = kt * BKF + lK;
        #pragma unroll
        for (int r = 0; r < 16; r++)
            areg[r] = A[(size_t)(m0 + arb + r * 8) * Ktot + k];
        int kb = kt * BKF + bkg;
        #pragma unroll
        for (int r = 0; r < 4; r++)
            breg[r] = *(const float4*)(Wfc + (size_t)(bnb + r * 32) * Ktot + kb);
    };
    auto sts = [&](int buf) {
        float* a = As + buf * BMF * LDKF;
        float* b = Bs + buf * BMF * LDKF;
        #pragma unroll
        for (int r = 0; r < 16; r++) a[(arb + r * 8) * LDKF + lK] = f2tf32(areg[r]);
        #pragma unroll
        for (int r = 0; r < 4; r++) {
            float4 v = breg[r];
            v.x = f2tf32(v.x); v.y = f2tf32(v.y); v.z = f2tf32(v.z); v.w = f2tf32(v.w);
            *(float4*)(b + (bnb + r * 32) * LDKF + bkg) = v;
        }
    };

    ldg(0); sts(0); __syncthreads();

    for (int kt = 0; kt < nkt; kt++) {
        if (kt + 1 < nkt) ldg(kt + 1);
        const float* a = As + (kt & 1) * BMF * LDKF;
        const float* b = Bs + (kt & 1) * BMF * LDKF;
        #pragma unroll
        for (int ks = 0; ks < BKF; ks += 8) {
            unsigned af[4][4], bf[4][2];
            #pragma unroll
            for (int mt = 0; mt < 4; mt++) {
                int row = wm * 64 + mt * 16 + g;
                af[mt][0] = __float_as_uint(a[row * LDKF + ks + tk]);
                af[mt][1] = __float_as_uint(a[(row + 8) * LDKF + ks + tk]);
                af[mt][2] = __float_as_uint(a[row * LDKF + ks + tk + 4]);
                af[mt][3] = __float_as_uint(a[(row + 8) * LDKF + ks + tk + 4]);
            }
            #pragma unroll
            for (int nt = 0; nt < 4; nt++) {
                int n = wn * 32 + nt * 8 + g;
                bf[nt][0] = __float_as_uint(b[n * LDKF + ks + tk]);
                bf[nt][1] = __float_as_uint(b[n * LDKF + ks + tk + 4]);
            }
            #pragma unroll
            for (int mt = 0; mt < 4; mt++)
                #pragma unroll
                for (int nt = 0; nt < 4; nt++)
                    mma_tf32(acc[mt][nt][0], acc[mt][nt][1], acc[mt][nt][2], acc[mt][nt][3],
                             af[mt][0], af[mt][1], af[mt][2], af[mt][3],
                             bf[nt][0], bf[nt][1]);
        }
        if (kt + 1 < nkt) { sts((kt + 1) & 1); __syncthreads(); }
    }

    __syncthreads();
    float* Cs = sm;
    #pragma unroll
    for (int mt = 0; mt < 4; mt++) {
        int row = wm * 64 + mt * 16 + g;
        #pragma unroll
        for (int nt = 0; nt < 4; nt++) {
            int col = wn * 32 + nt * 8 + 2 * tk;
            Cs[row * LDCF + col]           = acc[mt][nt][0];
            Cs[row * LDCF + col + 1]       = acc[mt][nt][1];
            Cs[(row + 8) * LDCF + col]     = acc[mt][nt][2];
            Cs[(row + 8) * LDCF + col + 1] = acc[mt][nt][3];
        }
    }
    __syncthreads();

    int ul  = tid & 31;
    int col = 4 * ul;
    float4 bb = *(const float4*)(bfc + col);
    #pragma unroll
    for (int r = 0; r < 16; r++) {
        int row = (tid >> 5) + 8 * r;
        float4 v = *(const float4*)(Cs + row * LDCF + col);
        v.x += bb.x; v.y += bb.y; v.z += bb.z; v.w += bb.w;
        *(float4*)(pred + (size_t)(m0 + row) * Nout + col) = v;
    }
}

// ---------------- launcher ----------------
extern "C" void kernel_launch(void* const* d_in, const int* in_sizes, int n_in,
                              void* d_out, int out_size)
{
    (void)in_sizes; (void)n_in; (void)out_size;
    const float* x    = (const float*)d_in[0];
    const float* h0in = (const float*)d_in[1];
    const float* Wfc = (const float*)d_in[29];
    const float* bfc = (const float*)d_in[30];

    float* out  = (float*)d_out;
    float* pred = out;
    float* hn   = out + (size_t)B_ * T_ * OUT_;

    cudaFuncSetAttribute(rnn_f16,   cudaFuncAttributeMaxDynamicSharedMemorySize, SMEM_DYN);
    cudaFuncSetAttribute(fc_kernel, cudaFuncAttributeMaxDynamicSharedMemorySize, SMEM_FC);

    // launch 1: x -> fp16 transposed
    {
        size_t n2 = (size_t)B_ * T_ * IDIM / 2;
        cvt_x<<<(unsigned)((n2 + 255) / 256), 256>>>(x);
    }
    // launch 2: all weights
    build_all<<<GB0 + GB1 + GB2, 256>>>(
        (const float*)d_in[3],  (const float*)d_in[4],  (const float*)d_in[5],  (const float*)d_in[6],
        (const float*)d_in[2],  (const float*)d_in[7],  (const float*)d_in[8],  (const float*)d_in[9],  (const float*)d_in[10],
        (const float*)d_in[12], (const float*)d_in[13], (const float*)d_in[14], (const float*)d_in[15],
        (const float*)d_in[11], (const float*)d_in[16], (const float*)d_in[17], (const float*)d_in[18], (const float*)d_in[19],
        (const float*)d_in[21], (const float*)d_in[22], (const float*)d_in[23], (const float*)d_in[24],
        (const float*)d_in[20], (const float*)d_in[25], (const float*)d_in[26], (const float*)d_in[27], (const float*)d_in[28]);
    // launch 3: h state init + barrier reset
    init_all<<<(IH0 + IH1 + IH2 + 255) / 256, 256>>>(h0in);

    // launch 4: the megakernel (ncu target)
    rnn_f16<<<NCTA, 256, SMEM_DYN>>>();

    fc_kernel<<<(B_ * T_) / BMF, 256, SMEM_FC>>>(pred, Wfc, bfc);
    write_hn<<<(B_ * UNITS + 255) / 256, 256>>>(hn);
}

// round 16
// speedup vs baseline: 1.1256x; 1.0069x over previous
#include <cuda_runtime.h>
#include <cuda_fp16.h>
#include <math.h>
#include <stdint.h>

// ---------------- problem dims ----------------
#define B_    512
#define T_    128
#define IDIM  512
#define N0    538
#define N1    358
#define N2    128
#define OUT_  128
#define UNITS 1024

// padded fp16 layouts (all K segments multiples of 64)
#define NP0   2176
#define KP0   1088      // [x 512 | h0 538->576]
#define NP1   1536
#define KP1   960       // [h0 576 | h1 358->384]
#define NP2   512
#define KP2   512       // [h1 384 | h2 128]
#define LH0   576
#define LH1   384
#define LH2   128

#define NCTA  132       // 68 L0 + 48 L1 + 16 L2
#define NTHR  512       // 16 warps

// tile: CTA 128x128, BK=64 per main-loop step
#define ROWB     144                 // stage row stride in bytes (128 data + 16 pad)
#define STAGEB   (128*ROWB)          // 18432 B per matrix per stage
#define LDC      132                 // C staging row stride (floats)
#define SMEM_DYN (4*STAGEB + 128)    // 73856 B; Cs (67584 B) aliases

// ---------------- device globals ----------------
__device__ __align__(16) __half g_x16[(size_t)B_ * T_ * IDIM];   // transposed: (T, B, IDIM)
__device__ __align__(16) __half g_w0[(size_t)NP0 * KP0];
__device__ __align__(16) __half g_w1[(size_t)NP1 * KP1];
__device__ __align__(16) __half g_w2[(size_t)NP2 * KP2];
__device__ __align__(16) float  g_bc0[NP0];
__device__ __align__(16) float  g_bc1[NP1];
__device__ __align__(16) float  g_bc2[NP2];
__device__ __align__(16) __half g_h16_0[2][B_ * LH0];
__device__ __align__(16) __half g_h16_1[2][B_ * LH1];
__device__ __align__(16) __half g_h16_2[2][B_ * LH2];
__device__ __align__(16) float  g_h32_0[B_ * N0];
__device__ __align__(16) float  g_h32_1[B_ * N1];
__device__ __align__(16) float  g_h32_2[B_ * N2];
__device__ __align__(16) float  g_motor[(size_t)B_ * T_ * OUT_];
__device__ unsigned g_bar_count;
__device__ unsigned g_bar_release;

// ---------------- PTX helpers ----------------
__device__ __forceinline__ uint32_t s2u(const void* p) {
    return (uint32_t)__cvta_generic_to_shared(p);
}
__device__ __forceinline__ void cpa16(uint32_t dst, const void* src) {
    asm volatile("cp.async.cg.shared.global [%0], [%1], 16;"
                 :: "r"(dst), "l"(src) : "memory");
}
#define CP_COMMIT() asm volatile("cp.async.commit_group;" ::: "memory")
#define CP_WAIT0()  asm volatile("cp.async.wait_group 0;" ::: "memory")

__device__ __forceinline__ void ldsm_x4(uint32_t& r0, uint32_t& r1, uint32_t& r2, uint32_t& r3,
                                        uint32_t addr)
{
    asm volatile("ldmatrix.sync.aligned.m8n8.x4.shared.b16 {%0,%1,%2,%3}, [%4];"
                 : "=r"(r0), "=r"(r1), "=r"(r2), "=r"(r3) : "r"(addr));
}
__device__ __forceinline__ void mma_f16(float& c0, float& c1, float& c2, float& c3,
                                        uint32_t a0, uint32_t a1, uint32_t a2, uint32_t a3,
                                        uint32_t b0, uint32_t b1)
{
    asm volatile("mma.sync.aligned.m16n8k16.row.col.f32.f16.f16.f32 "
                 "{%0,%1,%2,%3}, {%4,%5,%6,%7}, {%8,%9}, {%0,%1,%2,%3};"
                 : "+f"(c0), "+f"(c1), "+f"(c2), "+f"(c3)
                 : "r"(a0), "r"(a1), "r"(a2), "r"(a3), "r"(b0), "r"(b1));
}

// ---------------- prep kernels ----------------
// x (B,T,IDIM) fp32 -> g_x16 (T,B,IDIM) fp16            [launch 1]
__global__ void cvt_x(const float* __restrict__ x)
{
    size_t i = (size_t)blockIdx.x * blockDim.x + threadIdx.x;
    size_t n2 = (size_t)B_ * T_ * IDIM / 2;
    if (i >= n2) return;
    size_t e = i * 2;
    int b = (int)(e / (T_ * IDIM));
    int rem = (int)(e - (size_t)b * (T_ * IDIM));
    int t = rem / IDIM;
    int c = rem - t * IDIM;
    float2 v = ((const float2*)x)[i];
    ((__half2*)g_x16)[(((size_t)t * B_ + b) * IDIM + c) / 2] = __floats2half2_rn(v.x, v.y);
}

__device__ __forceinline__ void build_one(
    int idx,
    const float* __restrict__ W1, const float* __restrict__ W2,
    const float* __restrict__ Wa, const float* __restrict__ Wb,
    const float* __restrict__ mask,
    const float* __restrict__ b1, const float* __restrict__ b2,
    const float* __restrict__ ba, const float* __restrict__ bb,
    __half* __restrict__ Wc, float* __restrict__ bc,
    int n, int Korig, int k1real, int k1pad, int KP, int NP)
{
    if (idx < NP * KP) {
        int row = idx / KP, kp = idx - row * KP;
        float v = 0.f;
        if (row < 4 * n) {
            int kk = -1;
            if (kp < k1real) kk = kp;
            else if (kp >= k1pad && kp < k1pad + (Korig - k1real)) kk = k1real + (kp - k1pad);
            if (kk >= 0) {
                int j = row >> 2, g = row & 3;
                if (g == 0)      v = W1[(size_t)j * Korig + kk] * mask[(size_t)j * Korig + kk];
                else if (g == 1) v = W2[(size_t)j * Korig + kk] * mask[(size_t)j * Korig + kk];
                else if (g == 2) v = Wa[(size_t)j * Korig + kk];
                else             v = Wb[(size_t)j * Korig + kk];
            }
        }
        Wc[idx] = __float2half_rn(v);
    }
    if (idx < NP) {
        float v = 0.f;
        if (idx < 4 * n) {
            int j = idx >> 2, g = idx & 3;
            v = (g == 0) ? b1[j] : (g == 1) ? b2[j] : (g == 2) ? ba[j] : bb[j];
        }
        bc[idx] = v;
    }
}

#define GB0 9248
#define GB1 5760
#define GB2 1024

// single kernel building all 3 layers                    [launch 2]
__global__ void build_all(
    const float* W1_0, const float* W2_0, const float* Wa_0, const float* Wb_0,
    const float* mk_0, const float* b1_0, const float* b2_0, const float* ba_0, const float* bb_0,
    const float* W1_1, const float* W2_1, const float* Wa_1, const float* Wb_1,
    const float* mk_1, const float* b1_1, const float* b2_1, const float* ba_1, const float* bb_1,
    const float* W1_2, const float* W2_2, const float* Wa_2, const float* Wb_2,
    const float* mk_2, const float* b1_2, const float* b2_2, const float* ba_2, const float* bb_2)
{
    int blk = blockIdx.x;
    if (blk < GB0) {
        int idx = blk * 256 + threadIdx.x;
        build_one(idx, W1_0, W2_0, Wa_0, Wb_0, mk_0, b1_0, b2_0, ba_0, bb_0,
                  g_w0, g_bc0, N0, 1050, 512, 512, KP0, NP0);
    } else if (blk < GB0 + GB1) {
        int idx = (blk - GB0) * 256 + threadIdx.x;
        build_one(idx, W1_1, W2_1, Wa_1, Wb_1, mk_1, b1_1, b2_1, ba_1, bb_1,
                  g_w1, g_bc1, N1, 896, 538, 576, KP1, NP1);
    } else {
        int idx = (blk - GB0 - GB1) * 256 + threadIdx.x;
        build_one(idx, W1_2, W2_2, Wa_2, Wb_2, mk_2, b1_2, b2_2, ba_2, bb_2,
                  g_w2, g_bc2, N2, 486, 358, 384, KP2, NP2);
    }
}

// init h16 buffers + barrier reset                        [launch 3]
#define IH0 (2 * B_ * LH0)
#define IH1 (2 * B_ * LH1)
#define IH2 (2 * B_ * LH2)
__global__ void init_all(const float* __restrict__ h0in)
{
    int idx = blockIdx.x * blockDim.x + threadIdx.x;
    if (idx == 0) { g_bar_count = 0; g_bar_release = 0; }

    int r = idx;
    if (r < IH0) {
        int buf = r / (B_ * LH0); int e = r - buf * (B_ * LH0);
        int b = e / LH0, c = e - b * LH0;
        float v = (buf == 0 && c < N0) ? h0in[b * UNITS + c] : 0.f;
        g_h16_0[buf][e] = __float2half_rn(v);
        return;
    }
    r -= IH0;
    if (r < IH1) {
        int buf = r / (B_ * LH1); int e = r - buf * (B_ * LH1);
        int b = e / LH1, c = e - b * LH1;
        float v = (buf == 0 && c < N1) ? h0in[b * UNITS + N0 + c] : 0.f;
        g_h16_1[buf][e] = __float2half_rn(v);
        return;
    }
    r -= IH1;
    if (r < IH2) {
        int buf = r / (B_ * LH2); int e = r - buf * (B_ * LH2);
        int b = e / LH2, c = e - b * LH2;
        float v = (buf == 0) ? h0in[b * UNITS + N0 + N1 + c] : 0.f;
        g_h16_2[buf][e] = __float2half_rn(v);
    }
}

__global__ void write_hn(float* __restrict__ out)
{
    int idx = blockIdx.x * blockDim.x + threadIdx.x;
    if (idx >= B_ * UNITS) return;
    int b = idx / UNITS, c = idx - b * UNITS;
    float v;
    if (c < N0)           v = g_h32_0[b * N0 + c];
    else if (c < N0 + N1) v = g_h32_1[b * N1 + (c - N0)];
    else                  v = g_h32_2[b * N2 + (c - N0 - N1)];
    out[idx] = v;
}

// ---------------- grid barrier ----------------
__device__ __forceinline__ void grid_bar(int epoch)
{
    __syncthreads();
    if (threadIdx.x == 0) {
        __threadfence();
        unsigned a = atomicAdd(&g_bar_count, 1u) + 1u;
        if (a == (unsigned)(NCTA * epoch)) {
            asm volatile("st.global.release.gpu.u32 [%0], %1;"
                         :: "l"(&g_bar_release), "r"((unsigned)epoch) : "memory");
        } else {
            unsigned r;
            do {
                asm volatile("ld.global.acquire.gpu.u32 %0, [%1];"
                             : "=r"(r) : "l"(&g_bar_release) : "memory");
            } while (r < (unsigned)epoch);
        }
    }
    __syncthreads();
}

// ---------------- A segment base per (layer,t,64-chunk j), m0 applied ----------------
__device__ __forceinline__ const __half* a_base64(int layer, int t, int j, int m0, int& stride)
{
    if (layer == 0) {
        if (j < 8) { stride = IDIM; return g_x16 + ((size_t)t * B_ + m0) * IDIM + j * 64; }
        stride = LH0; return g_h16_0[t & 1] + (size_t)m0 * LH0 + (j - 8) * 64;
    } else if (layer == 1) {
        if (j < 9) { stride = LH0; return g_h16_0[1 - (t & 1)] + (size_t)m0 * LH0 + j * 64; }
        stride = LH1; return g_h16_1[t & 1] + (size_t)m0 * LH1 + (j - 9) * 64;
    } else {
        if (j < 6) { stride = LH1; return g_h16_1[1 - (t & 1)] + (size_t)m0 * LH1 + j * 64; }
        stride = LH2; return g_h16_2[t & 1] + (size_t)m0 * LH2 + (j - 6) * 64;
    }
}

// prefetch stage 0 of an L0 tile for step t (reads only x — dependency-free)
__device__ __forceinline__ void prefetch_l0_s0(int t, int m0, int n0, uint32_t sm_u32)
{
    uint32_t a_s = sm_u32;                 // buf 0
    uint32_t b_s = sm_u32 + 2 * STAGEB;    // buf 0
    const __half* ab = g_x16 + ((size_t)t * B_ + m0) * IDIM;   // j = 0
    const __half* wb = g_w0 + (size_t)n0 * KP0;
    int tid = threadIdx.x;
    #pragma unroll
    for (int i = 0; i < 2; i++) {
        int u = tid + i * NTHR;
        int r = u >> 3, q = u & 7;
        cpa16(a_s + r * ROWB + q * 16, ab + (size_t)r * IDIM + q * 8);
        cpa16(b_s + r * ROWB + q * 16, wb + (size_t)r * KP0 + q * 8);
    }
    CP_COMMIT();
}

// ---------------- one 128x128 tile (BK=64), 16 warps: 4M x 4N, 32x32 warp tiles ----------------
__device__ void run_tile(int layer, int t, int m0, int n0, char* smbase, bool pre)
{
    const __half* wbase; const float* bias; int KP, nkt;
    if (layer == 0)      { wbase = g_w0; bias = g_bc0; KP = KP0; nkt = KP0 / 64; }
    else if (layer == 1) { wbase = g_w1; bias = g_bc1; KP = KP1; nkt = KP1 / 64; }
    else                 { wbase = g_w2; bias = g_bc2; KP = KP2; nkt = KP2 / 64; }

    const uint32_t sm_u32 = s2u(smbase);
    const int tid  = threadIdx.x;
    const int lane = tid & 31;
    const int wid  = tid >> 5;
    const int wm   = wid & 3;        // 4 warps in M (32 rows each)
    const int wn   = wid >> 2;       // 4 warps in N (32 cols each)

    float acc[2][4][4];
    #pragma unroll
    for (int mt = 0; mt < 2; mt++)
        #pragma unroll
        for (int nt = 0; nt < 4; nt++)
            #pragma unroll
            for (int i = 0; i < 4; i++) acc[mt][nt][i] = 0.f;

    // fill one 64-wide stage: A 128x64 + B 128x64, 144B-padded rows (512 threads)
    auto fill = [&](int j) {
        int s = j & 1;
        uint32_t a_s = sm_u32 + s * STAGEB;
        uint32_t b_s = sm_u32 + 2 * STAGEB + s * STAGEB;
        int astr; const __half* ab = a_base64(layer, t, j, m0, astr);
        const __half* wb = wbase + (size_t)n0 * KP + j * 64;
        #pragma unroll
        for (int i = 0; i < 2; i++) {
            int u = tid + i * NTHR;
            int r = u >> 3, q = u & 7;
            cpa16(a_s + r * ROWB + q * 16, ab + (size_t)r * astr + q * 8);
            cpa16(b_s + r * ROWB + q * 16, wb + (size_t)r * KP + q * 8);
        }
        CP_COMMIT();
    };

    if (!pre) fill(0);

    for (int kt = 0; kt < nkt; kt++) {
        CP_WAIT0();           // stage kt complete (only outstanding group)
        __syncthreads();      // publish stage + retire previous compute
        if (kt + 1 < nkt) fill(kt + 1);   // overlaps with compute below

        int buf = kt & 1;
        uint32_t a_s = sm_u32 + buf * STAGEB;
        uint32_t b_s = sm_u32 + 2 * STAGEB + buf * STAGEB;

        #pragma unroll
        for (int ks = 0; ks < 64; ks += 16) {
            uint32_t af[2][4], bf[4][2];
            #pragma unroll
            for (int mt = 0; mt < 2; mt++) {
                int row = wm * 32 + mt * 16 + (lane & 15);
                uint32_t addr = a_s + row * ROWB + ks * 2 + (lane >> 4) * 16;
                ldsm_x4(af[mt][0], af[mt][1], af[mt][2], af[mt][3], addr);
            }
            #pragma unroll
            for (int j = 0; j < 2; j++) {
                int q = lane >> 3;
                int row = wn * 32 + 16 * j + (q >> 1) * 8 + (lane & 7);
                uint32_t addr = b_s + row * ROWB + (ks + (q & 1) * 8) * 2;
                ldsm_x4(bf[2 * j][0], bf[2 * j][1], bf[2 * j + 1][0], bf[2 * j + 1][1], addr);
            }
            #pragma unroll
            for (int mt = 0; mt < 2; mt++)
                #pragma unroll
                for (int nt = 0; nt < 4; nt++)
                    mma_f16(acc[mt][nt][0], acc[mt][nt][1], acc[mt][nt][2], acc[mt][nt][3],
                            af[mt][0], af[mt][1], af[mt][2], af[mt][3],
                            bf[nt][0], bf[nt][1]);
        }
    }

    // ---- epilogue: stage C in smem (aliases stage buffers), then gate ----
    __syncthreads();
    float* Cs = (float*)smbase;   // [128][LDC]
    {
        int g = lane >> 2, tk = lane & 3;
        #pragma unroll
        for (int mt = 0; mt < 2; mt++) {
            int row = wm * 32 + mt * 16 + g;
            #pragma unroll
            for (int nt = 0; nt < 4; nt++) {
                int col = wn * 32 + nt * 8 + 2 * tk;
                Cs[row * LDC + col]           = acc[mt][nt][0];
                Cs[row * LDC + col + 1]       = acc[mt][nt][1];
                Cs[(row + 8) * LDC + col]     = acc[mt][nt][2];
                Cs[(row + 8) * LDC + col + 1] = acc[mt][nt][3];
            }
        }
    }
    __syncthreads();

    // outputs
    __half* h16; int ldh;
    float *f1 = nullptr, *f2 = nullptr; int ldf1 = 0, ldf2 = 0, n1 = 0, nr2 = 0;
    int wp = 1 - (t & 1);
    bool last = (t == T_ - 1);
    if (layer == 0) {
        h16 = g_h16_0[wp]; ldh = LH0;
        if (last) { f1 = g_h32_0; ldf1 = N0; n1 = N0; }
    } else if (layer == 1) {
        h16 = g_h16_1[wp]; ldh = LH1;
        if (last) { f1 = g_h32_1; ldf1 = N1; n1 = N1; }
    } else {
        h16 = g_h16_2[wp]; ldh = LH2;
        f1 = g_motor + (size_t)t * OUT_; ldf1 = T_ * OUT_; n1 = N2;
        if (last) { f2 = g_h32_2; ldf2 = N2; nr2 = N2; }
    }

    {
        int ul = tid & 31;                 // 32 units per 128-col tile
        int u  = (n0 >> 2) + ul;
        float4 bb = *(const float4*)(bias + 4 * u);
        #pragma unroll
        for (int r = 0; r < 8; r++) {
            int row = (tid >> 5) + 16 * r;
            float4 v = *(const float4*)(Cs + row * LDC + 4 * ul);
            float ff1 = tanhf(v.x + bb.x);
            float ff2 = tanhf(v.y + bb.y);
            float s   = (v.z + bb.z) + (v.w + bb.w);
            float tg  = 1.f / (1.f + __expf(-s));
            float h   = ff1 + tg * (ff2 - ff1);
            size_t grow = (size_t)(m0 + row);
            h16[grow * ldh + u] = __float2half_rn(h);
            if (f1 && u < n1)  f1[grow * ldf1 + u] = h;
            if (f2 && u < nr2) f2[grow * ldf2 + u] = h;
        }
    }
    __syncthreads();   // all epilogue stores done before prefetch reuses smem
}

// ---------------- persistent wavefront kernel ----------------
__global__ __launch_bounds__(NTHR, 1)
void rnn_f16()
{
    extern __shared__ char smraw[];
    char* smbase = (char*)(((uintptr_t)smraw + 127) & ~(uintptr_t)127);
    const uint32_t sm_u32 = s2u(smbase);
    const int bid = blockIdx.x;

    int layer, mrow, ncol;
    if (bid < 68)       { layer = 0; mrow = bid & 3; ncol = bid >> 2; }
    else if (bid < 116) { layer = 1; int b = bid - 68;  mrow = b & 3; ncol = b >> 2; }
    else                { layer = 2; int b = bid - 116; mrow = b & 3; ncol = b >> 2; }

    for (int p = 0; p < T_ + 2; p++) {
        int t = p - layer;
        if (t >= 0 && t < T_)
            run_tile(layer, t, mrow * 128, ncol * 128, smbase,
                     (layer == 0 && t > 0));
        if (layer == 0 && t + 1 < T_)
            prefetch_l0_s0(t + 1, mrow * 128, ncol * 128, sm_u32);
        grid_bar(p + 1);
    }
}

// ================= tf32 path for the final FC (verified) =================
#define BMF 128
#define BKF 32
#define LDKF 36
#define LDCF 132
#define SMEM_FC (4*BMF*LDKF*4)

__device__ __forceinline__ float f2tf32(float f) {
    unsigned r;
    asm("cvt.rna.tf32.f32 %0, %1;" : "=r"(r) : "f"(f));
    return __uint_as_float(r);
}
__device__ __forceinline__ void mma_tf32(float& c0, float& c1, float& c2, float& c3,
                                         unsigned a0, unsigned a1, unsigned a2, unsigned a3,
                                         unsigned b0, unsigned b1)
{
    asm volatile("mma.sync.aligned.m16n8k8.row.col.f32.tf32.tf32.f32 "
                 "{%0,%1,%2,%3}, {%4,%5,%6,%7}, {%8,%9}, {%0,%1,%2,%3};"
                 : "+f"(c0), "+f"(c1), "+f"(c2), "+f"(c3)
                 : "r"(a0), "r"(a1), "r"(a2), "r"(a3), "r"(b0), "r"(b1));
}

__global__ __launch_bounds__(256)
void fc_kernel(float* __restrict__ pred, const float* __restrict__ Wfc,
               const float* __restrict__ bfc)
{
    extern __shared__ float sm[];
    float* As = sm;
    float* Bs = sm + 2 * BMF * LDKF;

    const float* A = g_motor;
    const int Ktot = OUT_;
    const int Nout = OUT_;

    const int tid  = threadIdx.x;
    const int lane = tid & 31;
    const int g    = lane >> 2;
    const int tk   = lane & 3;
    const int wid  = tid >> 5;
    const int wm   = wid & 1;
    const int wn   = wid >> 1;
    const int m0   = blockIdx.x * BMF;

    const int lK  = tid & 31;
    const int arb = tid >> 5;
    const int bkg = (tid & 7) * 4;
    const int bnb = tid >> 3;

    float acc[4][4][4];
    #pragma unroll
    for (int mt = 0; mt < 4; mt++)
        #pragma unroll
        for (int nt = 0; nt < 4; nt++)
            #pragma unroll
            for (int i = 0; i < 4; i++) acc[mt][nt][i] = 0.f;

    const int nkt = 128 / BKF;
    float areg[16]; float4 breg[4];

    auto ldg = [&](int kt) {
        int k = kt * BKF + lK;
        #pragma unroll
        for (int r = 0; r < 16; r++)
            areg[r] = A[(size_t)(m0 + arb + r * 8) * Ktot + k];
        int kb = kt * BKF + bkg;
        #pragma unroll
        for (int r = 0; r < 4; r++)
            breg[r] = *(const float4*)(Wfc + (size_t)(bnb + r * 32) * Ktot + kb);
    };
    auto sts = [&](int buf) {
        float* a = As + buf * BMF * LDKF;
        float* b = Bs + buf * BMF * LDKF;
        #pragma unroll
        for (int r = 0; r < 16; r++) a[(arb + r * 8) * LDKF + lK] = f2tf32(areg[r]);
        #pragma unroll
        for (int r = 0; r < 4; r++) {
            float4 v = breg[r];
            v.x = f2tf32(v.x); v.y = f2tf32(v.y); v.z = f2tf32(v.z); v.w = f2tf32(v.w);
            *(float4*)(b + (bnb + r * 32) * LDKF + bkg) = v;
        }
    };

    ldg(0); sts(0); __syncthreads();

    for (int kt = 0; kt < nkt; kt++) {
        if (kt + 1 < nkt) ldg(kt + 1);
        const float* a = As + (kt & 1) * BMF * LDKF;
        const float* b = Bs + (kt & 1) * BMF * LDKF;
        #pragma unroll
        for (int ks = 0; ks < BKF; ks += 8) {
            unsigned af[4][4], bf[4][2];
            #pragma unroll
            for (int mt = 0; mt < 4; mt++) {
                int row = wm * 64 + mt * 16 + g;
                af[mt][0] = __float_as_uint(a[row * LDKF + ks + tk]);
                af[mt][1] = __float_as_uint(a[(row + 8) * LDKF + ks + tk]);
                af[mt][2] = __float_as_uint(a[row * LDKF + ks + tk + 4]);
                af[mt][3] = __float_as_uint(a[(row + 8) * LDKF + ks + tk + 4]);
            }
            #pragma unroll
            for (int nt = 0; nt < 4; nt++) {
                int n = wn * 32 + nt * 8 + g;
                bf[nt][0] = __float_as_uint(b[n * LDKF + ks + tk]);
                bf[nt][1] = __float_as_uint(b[n * LDKF + ks + tk + 4]);
            }
            #pragma unroll
            for (int mt = 0; mt < 4; mt++)
                #pragma unroll
                for (int nt = 0; nt < 4; nt++)
                    mma_tf32(acc[mt][nt][0], acc[mt][nt][1], acc[mt][nt][2], acc[mt][nt][3],
                             af[mt][0], af[mt][1], af[mt][2], af[mt][3],
                             bf[nt][0], bf[nt][1]);
        }
        if (kt + 1 < nkt) { sts((kt + 1) & 1); __syncthreads(); }
    }

    __syncthreads();
    float* Cs = sm;
    #pragma unroll
    for (int mt = 0; mt < 4; mt++) {
        int row = wm * 64 + mt * 16 + g;
        #pragma unroll
        for (int nt = 0; nt < 4; nt++) {
            int col = wn * 32 + nt * 8 + 2 * tk;
            Cs[row * LDCF + col]           = acc[mt][nt][0];
            Cs[row * LDCF + col + 1]       = acc[mt][nt][1];
            Cs[(row + 8) * LDCF + col]     = acc[mt][nt][2];
            Cs[(row + 8) * LDCF + col + 1] = acc[mt][nt][3];
        }
    }
    __syncthreads();

    int ul  = tid & 31;
    int col = 4 * ul;
    float4 bb = *(const float4*)(bfc + col);
    #pragma unroll
    for (int r = 0; r < 16; r++) {
        int row = (tid >> 5) + 8 * r;
        float4 v = *(const float4*)(Cs + row * LDCF + col);
        v.x += bb.x; v.y += bb.y; v.z += bb.z; v.w += bb.w;
        *(float4*)(pred + (size_t)(m0 + row) * Nout + col) = v;
    }
}

// ---------------- launcher ----------------
extern "C" void kernel_launch(void* const* d_in, const int* in_sizes, int n_in,
                              void* d_out, int out_size)
{
    (void)in_sizes; (void)n_in; (void)out_size;
    const float* x    = (const float*)d_in[0];
    const float* h0in = (const float*)d_in[1];
    const float* Wfc = (const float*)d_in[29];
    const float* bfc = (const float*)d_in[30];

    float* out  = (float*)d_out;
    float* pred = out;
    float* hn   = out + (size_t)B_ * T_ * OUT_;

    cudaFuncSetAttribute(rnn_f16,   cudaFuncAttributeMaxDynamicSharedMemorySize, SMEM_DYN);
    cudaFuncSetAttribute(fc_kernel, cudaFuncAttributeMaxDynamicSharedMemorySize, SMEM_FC);

    // launch 1: x -> fp16 transposed
    {
        size_t n2 = (size_t)B_ * T_ * IDIM / 2;
        cvt_x<<<(unsigned)((n2 + 255) / 256), 256>>>(x);
    }
    // launch 2: all weights
    build_all<<<GB0 + GB1 + GB2, 256>>>(
        (const float*)d_in[3],  (const float*)d_in[4],  (const float*)d_in[5],  (const float*)d_in[6],
        (const float*)d_in[2],  (const float*)d_in[7],  (const float*)d_in[8],  (const float*)d_in[9],  (const float*)d_in[10],
        (const float*)d_in[12], (const float*)d_in[13], (const float*)d_in[14], (const float*)d_in[15],
        (const float*)d_in[11], (const float*)d_in[16], (const float*)d_in[17], (const float*)d_in[18], (const float*)d_in[19],
        (const float*)d_in[21], (const float*)d_in[22], (const float*)d_in[23], (const float*)d_in[24],
        (const float*)d_in[20], (const float*)d_in[25], (const float*)d_in[26], (const float*)d_in[27], (const float*)d_in[28]);
    // launch 3: h state init + barrier reset
    init_all<<<(IH0 + IH1 + IH2 + 255) / 256, 256>>>(h0in);

    // launch 4: the megakernel (ncu target)
    rnn_f16<<<NCTA, NTHR, SMEM_DYN>>>();

    fc_kernel<<<(B_ * T_) / BMF, 256, SMEM_FC>>>(pred, Wfc, bfc);
    write_hn<<<(B_ * UNITS + 255) / 256, 256>>>(hn);
}